// round 1
// baseline (speedup 1.0000x reference)
#include <cuda_runtime.h>

// DynamicUpsamplingFilter: out[b,c,h,w] = sum_{dy,dx} x_pad[b,c,h+dy,w+dx] * filters[b,dy*3+dx,h,w]
// x: [4,128,180,320] f32, filters: [4,9,180,320] f32, out: [4,128,180,320] f32.
//
// Strategy: one thread per (b,h,w) pixel. Load 9 filter taps + 9 clamped
// offsets into registers once, then stream all 128 channels. Filter values
// for out-of-bounds taps are zeroed (offset clamped to a legal address), so
// the inner loop is branch-free: 9 LDG + 9 FFMA per channel.
// HBM-bound: ~245 MB minimum traffic.

constexpr int B = 4, C = 128, H = 180, W = 320;
constexpr int HW = H * W;
constexpr int NPIX = B * HW;          // 230400
constexpr int THREADS = 256;

__global__ __launch_bounds__(THREADS)
void duf_kernel(const float* __restrict__ x,
                const float* __restrict__ f,
                float* __restrict__ out)
{
    int idx = blockIdx.x * THREADS + threadIdx.x;
    if (idx >= NPIX) return;

    int w  = idx % W;
    int hb = idx / W;
    int h  = hb % H;
    int b  = hb / H;

    // Load 9 filter taps for this pixel; zero the ones whose tap is OOB,
    // and clamp those offsets so the (dead) load stays in-bounds.
    const float* fp = f + (size_t)b * 9 * HW + (size_t)h * W + w;
    float fv[9];
    int   off[9];
#pragma unroll
    for (int dy = -1; dy <= 1; ++dy) {
#pragma unroll
        for (int dx = -1; dx <= 1; ++dx) {
            int i = (dy + 1) * 3 + (dx + 1);
            bool vy = (unsigned)(h + dy) < (unsigned)H;
            bool vx = (unsigned)(w + dx) < (unsigned)W;
            bool valid = vy && vx;
            float fval = fp[(size_t)i * HW];
            fv[i]  = valid ? fval : 0.0f;
            int cy = vy ? dy : 0;
            int cx = vx ? dx : 0;
            off[i] = cy * W + cx;
        }
    }

    const float* xp = x   + (size_t)b * C * HW + (size_t)h * W + w;
    float*       op = out + (size_t)b * C * HW + (size_t)h * W + w;

#pragma unroll 4
    for (int c = 0; c < C; ++c) {
        const float* xc = xp + (size_t)c * HW;
        float s = 0.0f;
#pragma unroll
        for (int i = 0; i < 9; ++i)
            s = fmaf(__ldg(xc + off[i]), fv[i], s);
        op[(size_t)c * HW] = s;
    }
}

extern "C" void kernel_launch(void* const* d_in, const int* in_sizes, int n_in,
                              void* d_out, int out_size)
{
    const float* x = (const float*)d_in[0];   // [4,128,180,320]
    const float* f = (const float*)d_in[1];   // [4,9,180,320]
    float* out = (float*)d_out;               // [4,128,180,320]

    int grid = (NPIX + THREADS - 1) / THREADS;   // 900
    duf_kernel<<<grid, THREADS>>>(x, f, out);
}

// round 2
// speedup vs baseline: 1.3500x; 1.3500x over previous
#include <cuda_runtime.h>

// DynamicUpsamplingFilter: out[b,c,h,w] = sum_{dy,dx} x_pad[b,c,h+dy,w+dx] * filters[b,dy*3+dx,h,w]
// x: [4,128,180,320] f32, filters: [4,9,180,320] f32, out: [4,128,180,320] f32.
//
// R2: each thread owns 4 consecutive w pixels (float4-aligned) and 32 channels.
// Per channel: 3 rows x (1 LDG.128 + 2 LDG.32) = 9 load instrs covering 4 pixels
// (vs 36 scalar loads), 36 FFMA, one STG.128. Filters: 9 LDG.128 per thread,
// held in registers across the channel loop. Boundaries: clamp addresses,
// zero the register-resident filter components -> branch-free inner loop.

constexpr int B = 4, C = 128, H = 180, W = 320;
constexpr int HW = H * W;
constexpr int WQ = W / 4;            // 80 pixel-quads per row
constexpr int CCH = 32;              // channels per thread
constexpr int NCQ = C / CCH;         // 4 channel-quads
constexpr int THREADS = 256;
constexpr int NTHREADS_TOTAL = B * NCQ * H * WQ;   // 230400
constexpr int GRID = NTHREADS_TOTAL / THREADS;     // 900

__global__ __launch_bounds__(THREADS)
void duf_kernel(const float* __restrict__ x,
                const float* __restrict__ f,
                float* __restrict__ out)
{
    int idx = blockIdx.x * THREADS + threadIdx.x;

    // consecutive threads -> consecutive wq for coalescing
    int wq = idx % WQ;
    int t  = idx / WQ;
    int h  = t % H;
    t /= H;
    int cq = t % NCQ;
    int b  = t / NCQ;
    int w  = wq * 4;

    // ---- load 9 filter tap vectors (pixels w..w+3) into registers ----
    const float* fp = f + (size_t)b * 9 * HW + (size_t)h * W + w;
    float4 fv[9];
#pragma unroll
    for (int i = 0; i < 9; ++i)
        fv[i] = *(const float4*)(fp + (size_t)i * HW);

    // vertical boundary: zero whole tap rows
    if (h == 0) {
#pragma unroll
        for (int i = 0; i < 3; ++i) fv[i] = make_float4(0.f, 0.f, 0.f, 0.f);
    }
    if (h == H - 1) {
#pragma unroll
        for (int i = 6; i < 9; ++i) fv[i] = make_float4(0.f, 0.f, 0.f, 0.f);
    }
    // horizontal boundary: pixel 0 loses dx=-1 taps, pixel 3 loses dx=+1 taps
    if (w == 0)     { fv[0].x = 0.f; fv[3].x = 0.f; fv[6].x = 0.f; }
    if (w == W - 4) { fv[2].w = 0.f; fv[5].w = 0.f; fv[8].w = 0.f; }

    // clamped offsets (dead loads land in-bounds; their filter is zero)
    int roff0 = (h > 0)      ? -W : 0;
    int roff2 = (h < H - 1)  ?  W : 0;
    int offm1 = (w > 0)      ? -1 : 0;   // column w-1
    int offp4 = (w + 4 < W)  ?  4 : 3;   // column w+4
    int roff[3] = { roff0, 0, roff2 };

    const float* xp = x   + ((size_t)b * C + cq * CCH) * HW + (size_t)h * W + w;
    float*       op = out + ((size_t)b * C + cq * CCH) * HW + (size_t)h * W + w;

#pragma unroll 2
    for (int c = 0; c < CCH; ++c) {
        const float* xc = xp + (size_t)c * HW;
        float a0 = 0.f, a1 = 0.f, a2 = 0.f, a3 = 0.f;
#pragma unroll
        for (int r = 0; r < 3; ++r) {
            const float* row = xc + roff[r];
            float4 m  = *(const float4*)row;  // columns w..w+3
            float vm1 = __ldg(row + offm1);   // column w-1
            float vp4 = __ldg(row + offp4);   // column w+4
            float4 F0 = fv[3 * r + 0];        // dx=-1 taps, pixels 0..3
            float4 F1 = fv[3 * r + 1];        // dx= 0
            float4 F2 = fv[3 * r + 2];        // dx=+1
            // pixel j uses v[j], v[j+1], v[j+2] with v = {vm1, m.x,m.y,m.z,m.w, vp4}
            a0 = fmaf(vm1, F0.x, a0); a0 = fmaf(m.x, F1.x, a0); a0 = fmaf(m.y, F2.x, a0);
            a1 = fmaf(m.x, F0.y, a1); a1 = fmaf(m.y, F1.y, a1); a1 = fmaf(m.z, F2.y, a1);
            a2 = fmaf(m.y, F0.z, a2); a2 = fmaf(m.z, F1.z, a2); a2 = fmaf(m.w, F2.z, a2);
            a3 = fmaf(m.z, F0.w, a3); a3 = fmaf(m.w, F1.w, a3); a3 = fmaf(vp4, F2.w, a3);
        }
        *(float4*)(op + (size_t)c * HW) = make_float4(a0, a1, a2, a3);
    }
}

extern "C" void kernel_launch(void* const* d_in, const int* in_sizes, int n_in,
                              void* d_out, int out_size)
{
    const float* x = (const float*)d_in[0];   // [4,128,180,320]
    const float* f = (const float*)d_in[1];   // [4,9,180,320]
    float* out = (float*)d_out;               // [4,128,180,320]

    duf_kernel<<<GRID, THREADS>>>(x, f, out);
}